// round 14
// baseline (speedup 1.0000x reference)
#include <cuda_runtime.h>
#include <math.h>

#define BS 8
#define F 16
#define NI 24
#define L 16384            // H*W
#define NGRP (L / 32)      // 512 groups of 32 px per batch
#define IH 8               // instances per warp in k_var (3 splits)
#define ST 128             // k_sums block size

// ---------------- scratch (no allocations; zero-init; kernels restore zeros) ----------
__device__ float    g_sumsP[BS][NI][32];   // padded: one 128B line per (b,i)
__device__ float    g_counts[BS][NI];
__device__ unsigned g_masks[BS][NGRP][NI];
__device__ float    g_varnum[BS];
__device__ float    g_varden[BS];
__device__ float    g_hinge[BS];
__device__ float    g_reg[BS];

__device__ __forceinline__ float sqrt_approx(float x) {
    float r;
    asm("sqrt.approx.f32 %0,%1;" : "=f"(r) : "f"(x));
    return r;
}

// ================= K1: fused masks + counts + sums (no inner-loop shfl) =============
// grid = (128, BS) -> 1024 blocks x 4 warps; warp per (b, 32-px group).
__global__ void __launch_bounds__(ST) k_sums(const float* __restrict__ inp,
                                             const int* __restrict__ tgt,
                                             const int* __restrict__ nobj) {
    const int b    = blockIdx.y;
    const int tid  = threadIdx.x;
    const int warp = tid >> 5;
    const int lane = tid & 31;
    const int f    = lane & 15;
    const int half = lane >> 4;
    const int g    = blockIdx.x * 4 + warp;    // 0..511
    const int l0   = g * 32;
    const int nb   = __ldg(nobj + b);

    __shared__ float tbl[4 * 16 * ST];         // 32KB nibble tables, lane-major
    __shared__ float sh_w[4][NI][32];          // 12KB per-lane partials
    __shared__ float sh_c[4][NI];

    // ---- input: 16 contiguous pixels of this lane's feature row (4x LDG.128) ----
    const float* ip = inp + ((size_t)b * F + f) * L + l0 + half * 16;
    float4 v0 = *(const float4*)(ip + 0);
    float4 v1 = *(const float4*)(ip + 4);
    float4 v2 = *(const float4*)(ip + 8);
    float4 v3 = *(const float4*)(ip + 12);

    // ---- target: 6 coalesced LDG.128; lanes cover 4 rows x 8 int4 per chunk ----
    const int rsel = lane >> 3;                // 0..3
    const int q4   = lane & 7;                 // int4 index within 32-px row
    const int* tb  = tgt + (size_t)b * NI * L + l0;
    unsigned w[6];
#pragma unroll
    for (int c = 0; c < 6; c++) {
        const int j = c * 4 + rsel;            // instance row (< NI=24 always, safe)
        int4 t = ((const int4*)(tb + (size_t)j * L))[q4];
        unsigned nib = (unsigned)(t.x != 0) | ((unsigned)(t.y != 0) << 1)
                     | ((unsigned)(t.z != 0) << 2) | ((unsigned)(t.w != 0) << 3);
        unsigned ww = nib << (4 * q4);
        ww |= __shfl_xor_sync(0xffffffffu, ww, 1);
        ww |= __shfl_xor_sync(0xffffffffu, ww, 2);
        ww |= __shfl_xor_sync(0xffffffffu, ww, 4);
        w[c] = ww;
        if (q4 == 0) {
            const bool valid = (j < nb);
            if (valid) g_masks[b][g][j] = ww;
            sh_c[warp][j] = valid ? (float)__popc(ww) : 0.f;
        }
    }

    // ---- broadcast ALL instance masks to every lane (hoisted; independent shfls) ----
    unsigned mall[NI];
#pragma unroll
    for (int c = 0; c < 6; c++) {
#pragma unroll
        for (int r = 0; r < 4; r++)
            mall[c * 4 + r] = __shfl_sync(0xffffffffu, w[c], r << 3);
    }

    // ---- build 4 nibble subset-sum tables (private column per tid, no sync) ----
    float p[16] = {v0.x, v0.y, v0.z, v0.w, v1.x, v1.y, v1.z, v1.w,
                   v2.x, v2.y, v2.z, v2.w, v3.x, v3.y, v3.z, v3.w};
#pragma unroll
    for (int n = 0; n < 4; n++) {
        float a0 = p[4*n], a1 = p[4*n+1], a2 = p[4*n+2], a3 = p[4*n+3];
        float s01 = a0+a1, s02 = a0+a2, s12 = a1+a2;
        float s03 = a0+a3, s13 = a1+a3, s23 = a2+a3;
        float s012 = s01+a2, s013 = s01+a3, s023 = s02+a3, s123 = s12+a3;
        float s0123 = s012+a3;
        float* T = &tbl[(n * 16) * ST + tid];
        T[ 0*ST] = 0.f;  T[ 1*ST] = a0;   T[ 2*ST] = a1;   T[ 3*ST] = s01;
        T[ 4*ST] = a2;   T[ 5*ST] = s02;  T[ 6*ST] = s12;  T[ 7*ST] = s012;
        T[ 8*ST] = a3;   T[ 9*ST] = s03;  T[10*ST] = s13;  T[11*ST] = s013;
        T[12*ST] = s23;  T[13*ST] = s023; T[14*ST] = s123; T[15*ST] = s0123;
    }

    // ---- per-instance lookups: extract -> 4 LDS -> 3 FADD -> STS (no shfl) ----
#pragma unroll
    for (int j = 0; j < NI; j++) {
        if (j >= nb) break;                    // nb warp-uniform
        unsigned sub = (mall[j] >> (half * 16)) & 0xffffu;
        float t0 = tbl[(( sub        & 15u)      ) * ST + tid];
        float t1 = tbl[(((sub >>  4) & 15u) + 16 ) * ST + tid];
        float t2 = tbl[(((sub >>  8) & 15u) + 32 ) * ST + tid];
        float t3 = tbl[(( sub >> 12       ) + 48 ) * ST + tid];
        sh_w[warp][j][lane] = (t0 + t1) + (t2 + t3);
    }
    __syncthreads();

    // ---- block tree-reduce (combines both pixel halves) -> one atomic per (i,f) ----
    for (int idx = tid; idx < NI * F; idx += ST) {
        int j = idx >> 4, ff = idx & 15;
        if (j < nb) {
            float s = (sh_w[0][j][ff] + sh_w[0][j][ff + 16])
                    + (sh_w[1][j][ff] + sh_w[1][j][ff + 16])
                    + (sh_w[2][j][ff] + sh_w[2][j][ff + 16])
                    + (sh_w[3][j][ff] + sh_w[3][j][ff + 16]);
            atomicAdd(&g_sumsP[b][j][ff], s);
        }
    }
    if (tid < NI && tid < nb) {
        float s = sh_c[0][tid] + sh_c[1][tid] + sh_c[2][tid] + sh_c[3][tid];
        atomicAdd(&g_counts[b][tid], s);
    }
}

// ================= K2: var_num + (block 0 per batch) hinge/reg/varden ===============
// grid = (96, BS): blockIdx.x = pairblk*3 + ih. Warp: 64 px (2 groups) x 8 instances.
__global__ void __launch_bounds__(256) k_var(const float* __restrict__ inp,
                                             const int* __restrict__ nobj) {
    const int b       = blockIdx.y;
    const int ih      = blockIdx.x % 3;
    const int pairblk = blockIdx.x / 3;        // 0..31
    const int tid  = threadIdx.x;
    const int lane = tid & 31;
    const int warp = tid >> 5;
    const int i0   = ih * IH;
    const int w0   = (pairblk * 8 + warp) * 64;
    const int px0  = w0 + 2 * lane;
    const int grp0 = w0 >> 5;
    const int nb   = __ldg(nobj + b);
    int ni = nb - i0; ni = ni < 0 ? 0 : (ni > IH ? IH : ni);

    __shared__ unsigned long long m2[NI * F];  // (m,m) duplicated pairs
    __shared__ unsigned long long smm[NI];     // (mm,mm) pairs
    __shared__ float red[8];
    __shared__ float sh_h, sh_r, sh_v;

    // ---- prologue: batch-b means from sums/counts ----
    for (int idx = tid; idx < NI * F; idx += 256) {
        int i = idx >> 4;
        float mval = 0.f;
        if (i < nb) {
            float c = g_counts[b][i];
            mval = g_sumsP[b][i][idx & 15] / (c > 0.f ? c : 1.f);
        }
        unsigned long long d;
        asm("mov.b64 %0,{%1,%2};" : "=l"(d) : "f"(mval), "f"(mval));
        m2[idx] = d;
    }
    if (tid == 0) { sh_h = 0.f; sh_r = 0.f; sh_v = 0.f; }
    __syncthreads();
    if (tid < NI) {
        float mm = 0.f;
#pragma unroll
        for (int ff = 0; ff < F; ff++) {
            float lo, hi;
            asm("mov.b64 {%0,%1},%2;" : "=f"(lo), "=f"(hi) : "l"(m2[tid * F + ff]));
            mm += lo * lo; (void)hi;
        }
        unsigned long long d;
        asm("mov.b64 %0,{%1,%2};" : "=l"(d) : "f"(mm), "f"(mm));
        smm[tid] = d;
    }
    __syncthreads();

    float local = 0.f;
    if (ni > 0) {
        const float* ib = inp + (size_t)b * F * L + px0;
        unsigned long long p2[F];
#pragma unroll
        for (int ff = 0; ff < F; ff++) {
            float2 v = *(const float2*)(ib + (size_t)ff * L);
            asm("mov.b64 %0,{%1,%2};" : "=l"(p2[ff]) : "f"(v.x), "f"(v.y));
        }
        unsigned long long qa = 0ull, qb = 0ull, qc = 0ull, qd = 0ull;
#pragma unroll
        for (int q = 0; q < 4; q++) {
            asm("fma.rn.f32x2 %0,%1,%2,%3;" : "=l"(qa) : "l"(p2[q]),    "l"(p2[q]),    "l"(qa));
            asm("fma.rn.f32x2 %0,%1,%2,%3;" : "=l"(qb) : "l"(p2[q+4]),  "l"(p2[q+4]),  "l"(qb));
            asm("fma.rn.f32x2 %0,%1,%2,%3;" : "=l"(qc) : "l"(p2[q+8]),  "l"(p2[q+8]),  "l"(qc));
            asm("fma.rn.f32x2 %0,%1,%2,%3;" : "=l"(qd) : "l"(p2[q+12]), "l"(p2[q+12]), "l"(qd));
        }
        unsigned long long ppP, tA, tB;
        asm("add.rn.f32x2 %0,%1,%2;" : "=l"(tA) : "l"(qa), "l"(qb));
        asm("add.rn.f32x2 %0,%1,%2;" : "=l"(tB) : "l"(qc), "l"(qd));
        asm("add.rn.f32x2 %0,%1,%2;" : "=l"(ppP) : "l"(tA), "l"(tB));

        const int lh = lane & 15;
        unsigned mw = 0;
        if (lh < IH && i0 + lh < nb) mw = g_masks[b][grp0 + (lane >> 4)][i0 + lh];

        const unsigned long long NEG2 = 0xC0000000C0000000ull;   // (-2.f,-2.f)

#pragma unroll
        for (int j = 0; j < IH; j++) {
            if (j >= ni) break;
            unsigned mi = __shfl_sync(0xffffffffu, mw, (lane & 16) + j);
            unsigned bits = (mi >> (2 * (lane & 15))) & 3u;
            if (bits) {
                unsigned long long a0 = 0ull, a1 = 0ull, b0 = 0ull, b1 = 0ull;
                const unsigned long long* mrow = &m2[(i0 + j) * F];
#pragma unroll
                for (int q = 0; q < 4; q++) {
                    asm("fma.rn.f32x2 %0,%1,%2,%3;" : "=l"(a0) : "l"(p2[q]),    "l"(mrow[q]),    "l"(a0));
                    asm("fma.rn.f32x2 %0,%1,%2,%3;" : "=l"(a1) : "l"(p2[q+4]),  "l"(mrow[q+4]),  "l"(a1));
                    asm("fma.rn.f32x2 %0,%1,%2,%3;" : "=l"(b0) : "l"(p2[q+8]),  "l"(mrow[q+8]),  "l"(b0));
                    asm("fma.rn.f32x2 %0,%1,%2,%3;" : "=l"(b1) : "l"(p2[q+12]), "l"(mrow[q+12]), "l"(b1));
                }
                unsigned long long s0, s1, dotP, base, ssP;
                asm("add.rn.f32x2 %0,%1,%2;" : "=l"(s0) : "l"(a0), "l"(a1));
                asm("add.rn.f32x2 %0,%1,%2;" : "=l"(s1) : "l"(b0), "l"(b1));
                asm("add.rn.f32x2 %0,%1,%2;" : "=l"(dotP) : "l"(s0), "l"(s1));
                asm("add.rn.f32x2 %0,%1,%2;" : "=l"(base) : "l"(ppP), "l"(smm[i0 + j]));
                asm("fma.rn.f32x2 %0,%1,%2,%3;" : "=l"(ssP) : "l"(NEG2), "l"(dotP), "l"(base));
                float ss0, ss1;
                asm("mov.b64 {%0,%1},%2;" : "=f"(ss0), "=f"(ss1) : "l"(ssP));
                // (sqrt(ss)-0.5)^2 = ss - sqrt(ss) + 0.25
                if ((bits & 1u) && ss0 > 0.25f)
                    local += (ss0 - sqrt_approx(ss0)) + 0.25f;
                if ((bits & 2u) && ss1 > 0.25f)
                    local += (ss1 - sqrt_approx(ss1)) + 0.25f;
            }
        }
    }

#pragma unroll
    for (int o = 16; o > 0; o >>= 1)
        local += __shfl_down_sync(0xffffffffu, local, o);
    if (lane == 0) red[warp] = local;
    __syncthreads();
    if (tid < 8) {
        float v = red[tid];
#pragma unroll
        for (int o = 4; o > 0; o >>= 1)
            v += __shfl_down_sync(0xffu, v, o);
        if (tid == 0) atomicAdd(&g_varnum[b], v);
    }

    // ---- block 0 of each batch: varden / reg / hinge from shared means ----
    if (blockIdx.x == 0) {
        if (tid < NI && tid < nb) {
            float mmv;
            { float lo, hi;
              asm("mov.b64 {%0,%1},%2;" : "=f"(lo), "=f"(hi) : "l"(smm[tid]));
              mmv = lo; (void)hi; }
            atomicAdd(&sh_v, g_counts[b][tid]);
            atomicAdd(&sh_r, mmv > 0.f ? sqrt_approx(mmv) : 0.f);
        }
        const float* fm = (const float*)m2;    // duplicated pairs: stride 2
        for (int idx = tid; idx < NI * NI; idx += 256) {
            int i = idx / NI, j = idx % NI;
            if (i < nb && j < nb && i != j) {
                float ss = 0.f;
#pragma unroll
                for (int ff = 0; ff < F; ff++) {
                    float d = fm[(i * F + ff) * 2] - fm[(j * F + ff) * 2];
                    ss += d * d;
                }
                float h = fmaxf(3.0f - sqrt_approx(ss), 0.f);  // margin = 2*delta_d
                atomicAdd(&sh_h, h * h);
            }
        }
        __syncthreads();
        if (tid == 0) {
            g_varden[b] = sh_v;
            g_reg[b]    = sh_r;
            g_hinge[b]  = sh_h;
        }
    }
}

// ================= K3: final combine + rezero ========================
__global__ void __launch_bounds__(256) k_final(const int* __restrict__ nobj_arr,
                                               float* __restrict__ out) {
    const int tid = threadIdx.x;
    if (tid < 32) {
        float var_t = 0.f, dist_t = 0.f, reg_t = 0.f;
        if (tid < BS) {
            var_t = g_varnum[tid] / g_varden[tid];
            float nf = (float)nobj_arr[tid];
            float denom = nf > 1.f ? nf * (nf - 1.f) : 1.f;
            dist_t = (nf > 1.f) ? g_hinge[tid] / denom : 0.f;
            reg_t = g_reg[tid] / nf;
        }
#pragma unroll
        for (int o = 4; o > 0; o >>= 1) {
            var_t  += __shfl_down_sync(0xffffffffu, var_t,  o);
            dist_t += __shfl_down_sync(0xffffffffu, dist_t, o);
            reg_t  += __shfl_down_sync(0xffffffffu, reg_t,  o);
        }
        if (tid == 0)
            out[0] = var_t / BS + dist_t / BS + 0.001f * (reg_t / BS);
    }
    // rezero scratch for next graph replay
    for (int idx = tid; idx < BS * NI * 32; idx += 256) ((float*)g_sumsP)[idx] = 0.f;
    if (tid < BS * NI) ((float*)g_counts)[tid] = 0.f;
    if (tid < BS) g_varnum[tid] = 0.f;
}

// ---------------- launch ----------------
extern "C" void kernel_launch(void* const* d_in, const int* in_sizes, int n_in,
                              void* d_out, int out_size) {
    const float* inp  = (const float*)d_in[0];   // (8,16,128,128) f32
    const int*   tgt  = (const int*)d_in[1];     // (8,24,128,128) i32
    const int*   nobj = (const int*)d_in[2];     // (8,1) i32
    (void)in_sizes; (void)n_in; (void)out_size;

    dim3 gs(128, BS);                            // 1024 blocks x 128 thr
    k_sums<<<gs, ST>>>(inp, tgt, nobj);
    dim3 gv(96, BS);                             // 768 blocks x 256 thr
    k_var<<<gv, 256>>>(inp, nobj);
    k_final<<<1, 256>>>(nobj, (float*)d_out);
}

// round 15
// speedup vs baseline: 1.7476x; 1.7476x over previous
#include <cuda_runtime.h>
#include <math.h>

#define BS 8
#define F 16
#define NI 24
#define L 16384            // H*W
#define NGRP (L / 32)      // 512 groups of 32 px per batch
#define IH 8               // instances per warp in k_var (3 splits)
#define ST 128             // k_sums block size

// ---------------- scratch (no allocations; zero-init; kernels restore zeros) ----------
__device__ float    g_sumsP[BS][NI][32];   // padded: one 128B line per (b,i)
__device__ float    g_counts[BS][NI];
__device__ unsigned g_masks[BS][NGRP][NI];
__device__ float    g_varnum[BS];
__device__ float    g_varden[BS];
__device__ float    g_hinge[BS];
__device__ float    g_reg[BS];

__device__ __forceinline__ float sqrt_approx(float x) {
    float r;
    asm("sqrt.approx.f32 %0,%1;" : "=f"(r) : "f"(x));
    return r;
}

// ================= K1: fused masks + counts + sums (R12 proven shape) ===============
// grid = (128, BS) -> 1024 blocks x 4 warps; warp per (b, 32-px group).
__global__ void __launch_bounds__(ST) k_sums(const float* __restrict__ inp,
                                             const int* __restrict__ tgt,
                                             const int* __restrict__ nobj) {
    const int b    = blockIdx.y;
    const int tid  = threadIdx.x;
    const int warp = tid >> 5;
    const int lane = tid & 31;
    const int f    = lane & 15;
    const int half = lane >> 4;
    const int g    = blockIdx.x * 4 + warp;    // 0..511
    const int l0   = g * 32;
    const int nb   = __ldg(nobj + b);

    __shared__ float tbl[4 * 16 * ST];         // 32KB nibble tables, lane-major
    __shared__ float sh_w[4][NI][F];           // 6KB warp partials
    __shared__ float sh_c[4][NI];

    // ---- input: 16 contiguous pixels of this lane's feature row (4x LDG.128) ----
    const float* ip = inp + ((size_t)b * F + f) * L + l0 + half * 16;
    float4 v0 = *(const float4*)(ip + 0);
    float4 v1 = *(const float4*)(ip + 4);
    float4 v2 = *(const float4*)(ip + 8);
    float4 v3 = *(const float4*)(ip + 12);

    // ---- target: 6 coalesced LDG.128; lanes cover 4 rows x 8 int4 per chunk ----
    const int rsel = lane >> 3;                // 0..3
    const int q4   = lane & 7;                 // int4 index within 32-px row
    const int* tb  = tgt + (size_t)b * NI * L + l0;
    unsigned w[6];
#pragma unroll
    for (int c = 0; c < 6; c++) {
        const int j = c * 4 + rsel;            // instance row (< NI=24 always, safe)
        int4 t = ((const int4*)(tb + (size_t)j * L))[q4];
        unsigned nib = (unsigned)(t.x != 0) | ((unsigned)(t.y != 0) << 1)
                     | ((unsigned)(t.z != 0) << 2) | ((unsigned)(t.w != 0) << 3);
        unsigned ww = nib << (4 * q4);
        ww |= __shfl_xor_sync(0xffffffffu, ww, 1);
        ww |= __shfl_xor_sync(0xffffffffu, ww, 2);
        ww |= __shfl_xor_sync(0xffffffffu, ww, 4);
        w[c] = ww;
        if (q4 == 0) {
            const bool valid = (j < nb);
            if (valid) g_masks[b][g][j] = ww;
            sh_c[warp][j] = valid ? (float)__popc(ww) : 0.f;
        }
    }

    // ---- build 4 nibble subset-sum tables (private column per tid, no sync) ----
    float p[16] = {v0.x, v0.y, v0.z, v0.w, v1.x, v1.y, v1.z, v1.w,
                   v2.x, v2.y, v2.z, v2.w, v3.x, v3.y, v3.z, v3.w};
#pragma unroll
    for (int n = 0; n < 4; n++) {
        float a0 = p[4*n], a1 = p[4*n+1], a2 = p[4*n+2], a3 = p[4*n+3];
        float s01 = a0+a1, s02 = a0+a2, s12 = a1+a2;
        float s03 = a0+a3, s13 = a1+a3, s23 = a2+a3;
        float s012 = s01+a2, s013 = s01+a3, s023 = s02+a3, s123 = s12+a3;
        float s0123 = s012+a3;
        float* T = &tbl[(n * 16) * ST + tid];
        T[ 0*ST] = 0.f;  T[ 1*ST] = a0;   T[ 2*ST] = a1;   T[ 3*ST] = s01;
        T[ 4*ST] = a2;   T[ 5*ST] = s02;  T[ 6*ST] = s12;  T[ 7*ST] = s012;
        T[ 8*ST] = a3;   T[ 9*ST] = s03;  T[10*ST] = s13;  T[11*ST] = s013;
        T[12*ST] = s23;  T[13*ST] = s023; T[14*ST] = s123; T[15*ST] = s0123;
    }

    // ---- per-instance lookups (dynamic loop; successive j's are independent) ----
    for (int j = 0; j < nb; j++) {
        unsigned mi  = __shfl_sync(0xffffffffu, w[j >> 2], (j & 3) << 3);
        unsigned sub = (mi >> (half * 16)) & 0xffffu;
        float t0 = tbl[(( sub        & 15u)      ) * ST + tid];
        float t1 = tbl[(((sub >>  4) & 15u) + 16 ) * ST + tid];
        float t2 = tbl[(((sub >>  8) & 15u) + 32 ) * ST + tid];
        float t3 = tbl[(( sub >> 12       ) + 48 ) * ST + tid];
        float a  = (t0 + t1) + (t2 + t3);
        a += __shfl_down_sync(0xffffffffu, a, 16);   // combine pixel-halves
        if (lane < 16) sh_w[warp][j][f] = a;
    }
    __syncthreads();

    // ---- block tree-reduce -> one global atomic per (i,f) / per i ----
    for (int idx = tid; idx < NI * F; idx += ST) {
        int j = idx >> 4, ff = idx & 15;
        if (j < nb) {
            float s = sh_w[0][j][ff] + sh_w[1][j][ff]
                    + sh_w[2][j][ff] + sh_w[3][j][ff];
            atomicAdd(&g_sumsP[b][j][ff], s);
        }
    }
    if (tid < NI && tid < nb) {
        float s = sh_c[0][tid] + sh_c[1][tid] + sh_c[2][tid] + sh_c[3][tid];
        atomicAdd(&g_counts[b][tid], s);
    }
}

// ================= K2: var_num + (block 0 per batch) hinge/reg/varden ===============
// grid = (96, BS): blockIdx.x = pairblk*3 + ih. Warp: 64 px (2 groups) x 8 instances.
__global__ void __launch_bounds__(256) k_var(const float* __restrict__ inp,
                                             const int* __restrict__ nobj) {
    const int b       = blockIdx.y;
    const int ih      = blockIdx.x % 3;
    const int pairblk = blockIdx.x / 3;        // 0..31
    const int tid  = threadIdx.x;
    const int lane = tid & 31;
    const int warp = tid >> 5;
    const int i0   = ih * IH;
    const int w0   = (pairblk * 8 + warp) * 64;
    const int px0  = w0 + 2 * lane;
    const int grp0 = w0 >> 5;
    const int nb   = __ldg(nobj + b);
    int ni = nb - i0; ni = ni < 0 ? 0 : (ni > IH ? IH : ni);

    // early exit: nothing to do and not the stats block
    if (ni == 0 && blockIdx.x != 0) return;

    __shared__ unsigned long long m2[NI * F];  // (m,m) duplicated pairs
    __shared__ unsigned long long smm[NI];     // (mm,mm) pairs
    __shared__ float red[8];
    __shared__ float sh_h, sh_r, sh_v;

    // ---- prologue: batch-b means from sums/counts ----
    for (int idx = tid; idx < NI * F; idx += 256) {
        int i = idx >> 4;
        float mval = 0.f;
        if (i < nb) {
            float c = g_counts[b][i];
            mval = g_sumsP[b][i][idx & 15] / (c > 0.f ? c : 1.f);
        }
        unsigned long long d;
        asm("mov.b64 %0,{%1,%2};" : "=l"(d) : "f"(mval), "f"(mval));
        m2[idx] = d;
    }
    if (tid == 0) { sh_h = 0.f; sh_r = 0.f; sh_v = 0.f; }
    __syncthreads();
    if (tid < NI) {
        float mm = 0.f;
#pragma unroll
        for (int ff = 0; ff < F; ff++) {
            float lo, hi;
            asm("mov.b64 {%0,%1},%2;" : "=f"(lo), "=f"(hi) : "l"(m2[tid * F + ff]));
            mm += lo * lo; (void)hi;
        }
        unsigned long long d;
        asm("mov.b64 %0,{%1,%2};" : "=l"(d) : "f"(mm), "f"(mm));
        smm[tid] = d;
    }
    __syncthreads();

    float local = 0.f;
    if (ni > 0) {
        const float* ib = inp + (size_t)b * F * L + px0;
        unsigned long long p2[F];
#pragma unroll
        for (int ff = 0; ff < F; ff++) {
            float2 v = *(const float2*)(ib + (size_t)ff * L);
            asm("mov.b64 %0,{%1,%2};" : "=l"(p2[ff]) : "f"(v.x), "f"(v.y));
        }
        unsigned long long qa = 0ull, qb = 0ull, qc = 0ull, qd = 0ull;
#pragma unroll
        for (int q = 0; q < 4; q++) {
            asm("fma.rn.f32x2 %0,%1,%2,%3;" : "=l"(qa) : "l"(p2[q]),    "l"(p2[q]),    "l"(qa));
            asm("fma.rn.f32x2 %0,%1,%2,%3;" : "=l"(qb) : "l"(p2[q+4]),  "l"(p2[q+4]),  "l"(qb));
            asm("fma.rn.f32x2 %0,%1,%2,%3;" : "=l"(qc) : "l"(p2[q+8]),  "l"(p2[q+8]),  "l"(qc));
            asm("fma.rn.f32x2 %0,%1,%2,%3;" : "=l"(qd) : "l"(p2[q+12]), "l"(p2[q+12]), "l"(qd));
        }
        unsigned long long ppP, tA, tB;
        asm("add.rn.f32x2 %0,%1,%2;" : "=l"(tA) : "l"(qa), "l"(qb));
        asm("add.rn.f32x2 %0,%1,%2;" : "=l"(tB) : "l"(qc), "l"(qd));
        asm("add.rn.f32x2 %0,%1,%2;" : "=l"(ppP) : "l"(tA), "l"(tB));

        const int lh = lane & 15;
        unsigned mw = 0;
        if (lh < IH && i0 + lh < nb) mw = g_masks[b][grp0 + (lane >> 4)][i0 + lh];

        const unsigned long long NEG2 = 0xC0000000C0000000ull;   // (-2.f,-2.f)

#pragma unroll
        for (int j = 0; j < IH; j++) {
            if (j >= ni) break;
            unsigned mi = __shfl_sync(0xffffffffu, mw, (lane & 16) + j);
            unsigned bits = (mi >> (2 * (lane & 15))) & 3u;
            if (bits) {
                unsigned long long a0 = 0ull, a1 = 0ull, b0 = 0ull, b1 = 0ull;
                const unsigned long long* mrow = &m2[(i0 + j) * F];
#pragma unroll
                for (int q = 0; q < 4; q++) {
                    asm("fma.rn.f32x2 %0,%1,%2,%3;" : "=l"(a0) : "l"(p2[q]),    "l"(mrow[q]),    "l"(a0));
                    asm("fma.rn.f32x2 %0,%1,%2,%3;" : "=l"(a1) : "l"(p2[q+4]),  "l"(mrow[q+4]),  "l"(a1));
                    asm("fma.rn.f32x2 %0,%1,%2,%3;" : "=l"(b0) : "l"(p2[q+8]),  "l"(mrow[q+8]),  "l"(b0));
                    asm("fma.rn.f32x2 %0,%1,%2,%3;" : "=l"(b1) : "l"(p2[q+12]), "l"(mrow[q+12]), "l"(b1));
                }
                unsigned long long s0, s1, dotP, base, ssP;
                asm("add.rn.f32x2 %0,%1,%2;" : "=l"(s0) : "l"(a0), "l"(a1));
                asm("add.rn.f32x2 %0,%1,%2;" : "=l"(s1) : "l"(b0), "l"(b1));
                asm("add.rn.f32x2 %0,%1,%2;" : "=l"(dotP) : "l"(s0), "l"(s1));
                asm("add.rn.f32x2 %0,%1,%2;" : "=l"(base) : "l"(ppP), "l"(smm[i0 + j]));
                asm("fma.rn.f32x2 %0,%1,%2,%3;" : "=l"(ssP) : "l"(NEG2), "l"(dotP), "l"(base));
                float ss0, ss1;
                asm("mov.b64 {%0,%1},%2;" : "=f"(ss0), "=f"(ss1) : "l"(ssP));
                // (sqrt(ss)-0.5)^2 = ss - sqrt(ss) + 0.25
                if ((bits & 1u) && ss0 > 0.25f)
                    local += (ss0 - sqrt_approx(ss0)) + 0.25f;
                if ((bits & 2u) && ss1 > 0.25f)
                    local += (ss1 - sqrt_approx(ss1)) + 0.25f;
            }
        }
    }

#pragma unroll
    for (int o = 16; o > 0; o >>= 1)
        local += __shfl_down_sync(0xffffffffu, local, o);
    if (lane == 0) red[warp] = local;
    __syncthreads();
    if (tid < 8) {
        float v = red[tid];
#pragma unroll
        for (int o = 4; o > 0; o >>= 1)
            v += __shfl_down_sync(0xffu, v, o);
        if (tid == 0) atomicAdd(&g_varnum[b], v);
    }

    // ---- block 0 of each batch: varden / reg / hinge from shared means ----
    if (blockIdx.x == 0) {
        if (tid < NI && tid < nb) {
            float mmv;
            { float lo, hi;
              asm("mov.b64 {%0,%1},%2;" : "=f"(lo), "=f"(hi) : "l"(smm[tid]));
              mmv = lo; (void)hi; }
            atomicAdd(&sh_v, g_counts[b][tid]);
            atomicAdd(&sh_r, mmv > 0.f ? sqrt_approx(mmv) : 0.f);
        }
        const float* fm = (const float*)m2;    // duplicated pairs: stride 2
        for (int idx = tid; idx < NI * NI; idx += 256) {
            int i = idx / NI, j = idx % NI;
            if (i < nb && j < nb && i != j) {
                float ss = 0.f;
#pragma unroll
                for (int ff = 0; ff < F; ff++) {
                    float d = fm[(i * F + ff) * 2] - fm[(j * F + ff) * 2];
                    ss += d * d;
                }
                float h = fmaxf(3.0f - sqrt_approx(ss), 0.f);  // margin = 2*delta_d
                atomicAdd(&sh_h, h * h);
            }
        }
        __syncthreads();
        if (tid == 0) {
            g_varden[b] = sh_v;
            g_reg[b]    = sh_r;
            g_hinge[b]  = sh_h;
        }
    }
}

// ================= K3: final combine + rezero ========================
__global__ void __launch_bounds__(256) k_final(const int* __restrict__ nobj_arr,
                                               float* __restrict__ out) {
    const int tid = threadIdx.x;
    if (tid < 32) {
        float var_t = 0.f, dist_t = 0.f, reg_t = 0.f;
        if (tid < BS) {
            var_t = g_varnum[tid] / g_varden[tid];
            float nf = (float)nobj_arr[tid];
            float denom = nf > 1.f ? nf * (nf - 1.f) : 1.f;
            dist_t = (nf > 1.f) ? g_hinge[tid] / denom : 0.f;
            reg_t = g_reg[tid] / nf;
        }
#pragma unroll
        for (int o = 4; o > 0; o >>= 1) {
            var_t  += __shfl_down_sync(0xffffffffu, var_t,  o);
            dist_t += __shfl_down_sync(0xffffffffu, dist_t, o);
            reg_t  += __shfl_down_sync(0xffffffffu, reg_t,  o);
        }
        if (tid == 0)
            out[0] = var_t / BS + dist_t / BS + 0.001f * (reg_t / BS);
    }
    // rezero scratch for next graph replay
    for (int idx = tid; idx < BS * NI * 32; idx += 256) ((float*)g_sumsP)[idx] = 0.f;
    if (tid < BS * NI) ((float*)g_counts)[tid] = 0.f;
    if (tid < BS) g_varnum[tid] = 0.f;
}

// ---------------- launch ----------------
extern "C" void kernel_launch(void* const* d_in, const int* in_sizes, int n_in,
                              void* d_out, int out_size) {
    const float* inp  = (const float*)d_in[0];   // (8,16,128,128) f32
    const int*   tgt  = (const int*)d_in[1];     // (8,24,128,128) i32
    const int*   nobj = (const int*)d_in[2];     // (8,1) i32
    (void)in_sizes; (void)n_in; (void)out_size;

    dim3 gs(128, BS);                            // 1024 blocks x 128 thr
    k_sums<<<gs, ST>>>(inp, tgt, nobj);
    dim3 gv(96, BS);                             // 768 blocks x 256 thr
    k_var<<<gv, 256>>>(inp, nobj);
    k_final<<<1, 256>>>(nobj, (float*)d_out);
}